// round 13
// baseline (speedup 1.0000x reference)
#include <cuda_runtime.h>
#include <cuda_bf16.h>
#include <cstdint>

#define B_   2
#define C_   384
#define L_   8192
#define DIN  768
#define NST  16
#define DTR  24
#define XW   56        // dt_rank + 2*d_state
#define XWP  64        // padded rows of W_xproj for HMMA
#define SEG  16
#define SEGL (L_/SEG)  // 512

// ---------------- scratch (device globals; no allocation allowed) ----------------
__device__ float g_xi  [(size_t)B_*L_*DIN];    // (b*l, d)
__device__ float g_z   [(size_t)B_*L_*DIN];    // (b*l, d)
__device__ float g_xlt [(size_t)B_*L_*DIN];    // (b*l, d)  conv+silu output fp32 (scan)
__device__ float g_xdbl[(size_t)B_*L_*XW];     // (b*l, 56)
__device__ float g_dtl [(size_t)B_*L_*DIN];    // (b*l, d)  softplus(dt)
__device__ float g_segF[(size_t)B_*DIN*SEG*NST];   // segment final state (h0=0)
__device__ float g_segG[(size_t)B_*DIN*SEG*NST];   // segment decay
__device__ float g_segH[(size_t)B_*DIN*SEG*NST];   // segment entry state

// bf16 split operands for tensor-core GEMMs
__device__ __nv_bfloat16 g_xnh[(size_t)B_*L_*C_], g_xnl[(size_t)B_*L_*C_];       // xn   (b*l, c)
__device__ __nv_bfloat16 g_winh[(size_t)2*DIN*C_], g_winl[(size_t)2*DIN*C_];     // W_in
__device__ __nv_bfloat16 g_xch[(size_t)B_*L_*DIN], g_xcl[(size_t)B_*L_*DIN];     // xc   (b*l, d)
__device__ __nv_bfloat16 g_wxh[(size_t)XWP*DIN], g_wxl[(size_t)XWP*DIN];         // W_xproj padded
__device__ __nv_bfloat16 g_gh [(size_t)B_*L_*DIN], g_gl [(size_t)B_*L_*DIN];     // y*silu(z)
__device__ __nv_bfloat16 g_wouth[(size_t)C_*DIN], g_woutl[(size_t)C_*DIN];       // W_out

__device__ __forceinline__ float silu_f(float v) {
    return v * (1.f / (1.f + __expf(-v)));
}
__device__ __forceinline__ uint32_t smem_u32(const void* p) {
    uint32_t a;
    asm("{ .reg .u64 t; cvta.to.shared.u64 t, %1; cvt.u32.u64 %0, t; }" : "=r"(a) : "l"(p));
    return a;
}

// ================= async-copy / HMMA building blocks (base sm_103 legal) =================
#define CP16(dst, src) \
    asm volatile("cp.async.cg.shared.global [%0], [%1], 16;" :: "r"(dst), "l"(src))
#define CP_COMMIT() asm volatile("cp.async.commit_group;" ::: "memory")
#define CP_WAIT1()  asm volatile("cp.async.wait_group 1;" ::: "memory")
#define CP_WAIT0()  asm volatile("cp.async.wait_group 0;" ::: "memory")

__device__ __forceinline__ void ldsm4(uint32_t r[4], uint32_t addr) {
    asm volatile("ldmatrix.sync.aligned.m8n8.x4.shared.b16 {%0,%1,%2,%3}, [%4];"
        : "=r"(r[0]), "=r"(r[1]), "=r"(r[2]), "=r"(r[3]) : "r"(addr));
}
__device__ __forceinline__ void mma16816(float d[4], const uint32_t a[4],
                                         uint32_t b0, uint32_t b1) {
    asm volatile("mma.sync.aligned.m16n8k16.row.col.f32.bf16.bf16.f32 "
        "{%0,%1,%2,%3}, {%4,%5,%6,%7}, {%8,%9}, {%0,%1,%2,%3};"
        : "+f"(d[0]), "+f"(d[1]), "+f"(d[2]), "+f"(d[3])
        : "r"(a[0]), "r"(a[1]), "r"(a[2]), "r"(a[3]), "r"(b0), "r"(b1));
}

// ---------- 128x128 mainloop: 3-stage cp.async pipeline, one barrier per chunk ----------
__device__ __forceinline__ void stage_chunk(uint32_t sbuf,
        const __nv_bfloat16* __restrict__ Ah, const __nv_bfloat16* __restrict__ Al,
        int arow0, int lda,
        const __nv_bfloat16* __restrict__ Bh, const __nv_bfloat16* __restrict__ Bl,
        int brow0, int ldb, int kc, int tid) {
    const __nv_bfloat16* srcs[4] = {Ah, Al, Bh, Bl};
    #pragma unroll
    for (int tile = 0; tile < 4; tile++) {
        const __nv_bfloat16* src = srcs[tile];
        int ld = (tile < 2) ? lda : ldb;
        int r0 = (tile < 2) ? arow0 : brow0;
        #pragma unroll
        for (int h = 0; h < 2; h++) {
            int cid = tid + h * 256;
            int row = cid >> 2, ch = cid & 3;
            const void* g = src + (size_t)(r0 + row) * ld + kc * 32 + ch * 8;
            uint32_t d = sbuf + tile * 8192 + row * 64 + ((ch ^ ((row >> 1) & 3)) << 4);
            CP16(d, g);
        }
    }
}
__device__ __forceinline__ void compute_chunk(uint32_t sbuf, int warp_m, int warp_n,
                                              int lane, float acc[4][4][4]) {
    int arow = lane & 15;
    int akc  = lane >> 4;
    int bro  = (lane & 7) + ((lane >> 4) << 3);
    int bkc  = (lane >> 3) & 1;
    #pragma unroll
    for (int k16 = 0; k16 < 2; k16++) {
        uint32_t ah[4][4], al[4][4], bhf[2][4], blf[2][4];
        #pragma unroll
        for (int mi = 0; mi < 4; mi++) {
            int row = warp_m * 64 + mi * 16 + arow;
            int ch = k16 * 2 + akc;
            uint32_t off = row * 64 + ((ch ^ ((row >> 1) & 3)) << 4);
            ldsm4(ah[mi], sbuf + off);
            ldsm4(al[mi], sbuf + 8192 + off);
        }
        #pragma unroll
        for (int p = 0; p < 2; p++) {
            int row = warp_n * 32 + p * 16 + bro;
            int ch = k16 * 2 + bkc;
            uint32_t off = row * 64 + ((ch ^ ((row >> 1) & 3)) << 4);
            ldsm4(bhf[p], sbuf + 16384 + off);
            ldsm4(blf[p], sbuf + 24576 + off);
        }
        #pragma unroll
        for (int mi = 0; mi < 4; mi++)
            #pragma unroll
            for (int nj = 0; nj < 4; nj++) {
                int p = nj >> 1, w = (nj & 1) * 2;
                mma16816(acc[mi][nj], ah[mi], bhf[p][w], bhf[p][w + 1]);
                mma16816(acc[mi][nj], ah[mi], blf[p][w], blf[p][w + 1]);
                mma16816(acc[mi][nj], al[mi], bhf[p][w], bhf[p][w + 1]);
            }
    }
}
__device__ __forceinline__ void mma_mainloop(char* smem, int tid,
        const __nv_bfloat16* Ah, const __nv_bfloat16* Al, int arow0, int lda,
        const __nv_bfloat16* Bh, const __nv_bfloat16* Bl, int brow0, int ldb,
        int nch, float acc[4][4][4]) {
    uint32_t sb = smem_u32(smem);
    int warp_m = (tid >> 5) >> 2, warp_n = (tid >> 5) & 3, lane = tid & 31;
    #pragma unroll
    for (int mi = 0; mi < 4; mi++)
        #pragma unroll
        for (int nj = 0; nj < 4; nj++)
            #pragma unroll
            for (int r = 0; r < 4; r++) acc[mi][nj][r] = 0.f;
    stage_chunk(sb, Ah, Al, arow0, lda, Bh, Bl, brow0, ldb, 0, tid);
    CP_COMMIT();
    stage_chunk(sb + 32768, Ah, Al, arow0, lda, Bh, Bl, brow0, ldb, 1, tid);
    CP_COMMIT();
    for (int c = 0; c < nch; c++) {
        if (c + 1 < nch) CP_WAIT1(); else CP_WAIT0();
        __syncthreads();
        compute_chunk(sb + (c % 3) * 32768, warp_m, warp_n, lane, acc);
        if (c + 2 < nch) {
            stage_chunk(sb + ((c + 2) % 3) * 32768, Ah, Al, arow0, lda,
                        Bh, Bl, brow0, ldb, c + 2, tid);
            CP_COMMIT();
        }
    }
}
#define SMEM_HMMA (3 * 32768)

// ---------- 128x64 mainloop for xproj (2-stage, proven) ----------
__device__ __forceinline__ void stage_chunk_x(uint32_t sbuf, int kc, int arow0, int tid) {
    #pragma unroll
    for (int h = 0; h < 2; h++) {
        int cid = tid + h * 256;
        int row = cid >> 2, ch = cid & 3;
        const void* gh_ = g_xch + (size_t)(arow0 + row) * DIN + kc * 32 + ch * 8;
        const void* gl_ = g_xcl + (size_t)(arow0 + row) * DIN + kc * 32 + ch * 8;
        uint32_t off = row * 64 + ((ch ^ ((row >> 1) & 3)) << 4);
        CP16(sbuf + off, gh_);
        CP16(sbuf + 8192 + off, gl_);
    }
    {
        int row = tid >> 2, ch = tid & 3;
        const void* gh_ = g_wxh + (size_t)row * DIN + kc * 32 + ch * 8;
        const void* gl_ = g_wxl + (size_t)row * DIN + kc * 32 + ch * 8;
        uint32_t off = row * 64 + ((ch ^ ((row >> 1) & 3)) << 4);
        CP16(sbuf + 16384 + off, gh_);
        CP16(sbuf + 20480 + off, gl_);
    }
}
__device__ __forceinline__ void compute_chunk_x(uint32_t sbuf, int warp_m, int warp_n,
                                                int lane, float acc[2][4][4]) {
    int arow = lane & 15;
    int akc  = lane >> 4;
    int bro  = (lane & 7) + ((lane >> 4) << 3);
    int bkc  = (lane >> 3) & 1;
    #pragma unroll
    for (int k16 = 0; k16 < 2; k16++) {
        uint32_t ah[2][4], al[2][4], bhf[2][4], blf[2][4];
        #pragma unroll
        for (int mi = 0; mi < 2; mi++) {
            int row = warp_m * 32 + mi * 16 + arow;
            int ch = k16 * 2 + akc;
            uint32_t off = row * 64 + ((ch ^ ((row >> 1) & 3)) << 4);
            ldsm4(ah[mi], sbuf + off);
            ldsm4(al[mi], sbuf + 8192 + off);
        }
        #pragma unroll
        for (int p = 0; p < 2; p++) {
            int row = warp_n * 32 + p * 16 + bro;
            int ch = k16 * 2 + bkc;
            uint32_t off = row * 64 + ((ch ^ ((row >> 1) & 3)) << 4);
            ldsm4(bhf[p], sbuf + 16384 + off);
            ldsm4(blf[p], sbuf + 20480 + off);
        }
        #pragma unroll
        for (int mi = 0; mi < 2; mi++)
            #pragma unroll
            for (int nj = 0; nj < 4; nj++) {
                int p = nj >> 1, w = (nj & 1) * 2;
                mma16816(acc[mi][nj], ah[mi], bhf[p][w], bhf[p][w + 1]);
                mma16816(acc[mi][nj], ah[mi], blf[p][w], blf[p][w + 1]);
                mma16816(acc[mi][nj], al[mi], bhf[p][w], bhf[p][w + 1]);
            }
    }
}
#define SMEM_X (2 * 24576)

__global__ void __launch_bounds__(256) hmma_xproj_kernel() {
    extern __shared__ char smem[];
    uint32_t sb = smem_u32(smem);
    int tid = threadIdx.x;
    int bm = blockIdx.x;
    int arow0 = bm * 128;
    int warp = tid >> 5, lane = tid & 31;
    int warp_m = warp >> 1, warp_n = warp & 1;
    float acc[2][4][4];
    #pragma unroll
    for (int mi = 0; mi < 2; mi++)
        #pragma unroll
        for (int nj = 0; nj < 4; nj++)
            #pragma unroll
            for (int r = 0; r < 4; r++) acc[mi][nj][r] = 0.f;
    stage_chunk_x(sb, 0, arow0, tid);
    CP_COMMIT();
    const int nch = DIN / 32;
    for (int c = 0; c < nch; c++) {
        if (c + 1 < nch) {
            stage_chunk_x(sb + ((c + 1) & 1) * 24576, c + 1, arow0, tid);
            CP_COMMIT();
            CP_WAIT1();
        } else {
            CP_WAIT0();
        }
        __syncthreads();
        compute_chunk_x(sb + (c & 1) * 24576, warp_m, warp_n, lane, acc);
        __syncthreads();
    }
    int g = lane >> 2, t = lane & 3;
    #pragma unroll
    for (int mi = 0; mi < 2; mi++) {
        int row = arow0 + warp_m * 32 + mi * 16 + g;
        #pragma unroll
        for (int nj = 0; nj < 4; nj++) {
            int col = warp_n * 32 + nj * 8 + 2 * t;
            if (col < XW) {
                *(float2*)(g_xdbl + (size_t)row * XW + col)       = make_float2(acc[mi][nj][0], acc[mi][nj][1]);
                *(float2*)(g_xdbl + (size_t)(row + 8) * XW + col) = make_float2(acc[mi][nj][2], acc[mi][nj][3]);
            }
        }
    }
}

// ---------------- tensor GEMM 1: xz = xn @ W_in^T -> g_xi / g_z ----------------
__global__ void __launch_bounds__(256) hmma_gemm_in_kernel() {
    extern __shared__ char smem[];
    int tid = threadIdx.x;
    int bn = blockIdx.x, bm = blockIdx.y;
    float acc[4][4][4];
    mma_mainloop(smem, tid, g_xnh, g_xnl, bm * 128, C_,
                 g_winh, g_winl, bn * 128, C_, C_ / 32, acc);
    int warp_m = (tid >> 5) >> 2, warp_n = (tid >> 5) & 3, lane = tid & 31;
    int g = lane >> 2, t = lane & 3;
    int col0 = bn * 128;
    float* dst = (col0 < DIN) ? g_xi : g_z;
    int cbase = ((col0 < DIN) ? col0 : col0 - DIN) + warp_n * 32;
    #pragma unroll
    for (int mi = 0; mi < 4; mi++) {
        int row = bm * 128 + warp_m * 64 + mi * 16 + g;
        #pragma unroll
        for (int nj = 0; nj < 4; nj++) {
            int col = cbase + nj * 8 + 2 * t;
            *(float2*)(dst + (size_t)row * DIN + col)       = make_float2(acc[mi][nj][0], acc[mi][nj][1]);
            *(float2*)(dst + (size_t)(row + 8) * DIN + col) = make_float2(acc[mi][nj][2], acc[mi][nj][3]);
        }
    }
}

// ---------------- tensor GEMM 2: out = W_out x gate^T, store (b,c,l) ----------------
__global__ void __launch_bounds__(256) hmma_gemm_out_kernel(float* __restrict__ out) {
    extern __shared__ char smem[];
    int tid = threadIdx.x;
    int bn = blockIdx.x, bm = blockIdx.y;
    float acc[4][4][4];
    mma_mainloop(smem, tid, g_wouth, g_woutl, bm * 128, DIN,
                 g_gh, g_gl, bn * 128, DIN, DIN / 32, acc);
    int warp_m = (tid >> 5) >> 2, warp_n = (tid >> 5) & 3, lane = tid & 31;
    int g = lane >> 2, t = lane & 3;
    int nrow0 = bn * 128 + warp_n * 32;
    int b = nrow0 / L_;
    #pragma unroll
    for (int mi = 0; mi < 4; mi++) {
        int c = bm * 128 + warp_m * 64 + mi * 16 + g;
        #pragma unroll
        for (int nj = 0; nj < 4; nj++) {
            int l = (nrow0 % L_) + nj * 8 + 2 * t;
            *(float2*)(out + ((size_t)(b * C_ + c)) * L_ + l)     = make_float2(acc[mi][nj][0], acc[mi][nj][1]);
            *(float2*)(out + ((size_t)(b * C_ + c + 8)) * L_ + l) = make_float2(acc[mi][nj][2], acc[mi][nj][3]);
        }
    }
}

// ---------------- weight splits ----------------
#define N_WIN  (2*DIN*C_)
#define N_WOUT (C_*DIN)
#define N_WX   (XWP*DIN)
__global__ void cvt_w1_kernel(const float* __restrict__ W_in) {
    int i = blockIdx.x * 256 + threadIdx.x;
    if (i >= N_WIN) return;
    float v = W_in[i];
    __nv_bfloat16 hi = __float2bfloat16(v);
    g_winh[i] = hi;
    g_winl[i] = __float2bfloat16(v - __bfloat162float(hi));
}
__global__ void cvt_w2_kernel(const float* __restrict__ W_out, const float* __restrict__ Wx) {
    int i = blockIdx.x * 256 + threadIdx.x;
    float v; __nv_bfloat16 *h, *l; int j;
    if (i < N_WOUT) {
        j = i; v = W_out[j]; h = g_wouth; l = g_woutl;
    } else if (i < N_WOUT + N_WX) {
        j = i - N_WOUT;
        int r = j / DIN;
        v = (r < XW) ? Wx[(size_t)r * DIN + (j % DIN)] : 0.f;
        h = g_wxh; l = g_wxl;
    } else return;
    __nv_bfloat16 hi = __float2bfloat16(v);
    h[j] = hi;
    l[j] = __float2bfloat16(v - __bfloat162float(hi));
}

// ---------------- fused LayerNorm: stats + apply + transpose + bf16 split ----------------
__global__ void __launch_bounds__(256) ln_fused_kernel(const float* __restrict__ x,
        const float* __restrict__ w, const float* __restrict__ bb) {
    __shared__ float s[C_ * 17];          // [c][l] stride 17
    __shared__ float rs_[256], rss[256];
    __shared__ float smu[16], srs[16];
    int l0 = blockIdx.x * 16, b = blockIdx.y;
    int tid = threadIdx.x;
    #pragma unroll
    for (int q = 0; q < 6; q++) {
        int id = tid + q * 256;
        int c = id >> 2, j = id & 3;
        float4 v = *(const float4*)(x + ((size_t)(b * C_ + c)) * L_ + l0 + j * 4);
        float* p = s + c * 17 + j * 4;
        p[0] = v.x; p[1] = v.y; p[2] = v.z; p[3] = v.w;
    }
    __syncthreads();
    {
        int l = tid & 15, gr = tid >> 4;
        float sum = 0.f, ss = 0.f;
        for (int c = gr; c < C_; c += 16) {
            float v = s[c * 17 + l];
            sum += v; ss += v * v;
        }
        rs_[tid] = sum; rss[tid] = ss;
        __syncthreads();
        #pragma unroll
        for (int off = 8; off > 0; off >>= 1) {
            if (gr < off) { rs_[tid] += rs_[tid + off * 16]; rss[tid] += rss[tid + off * 16]; }
            __syncthreads();
        }
        if (gr == 0) {
            float mu = rs_[l] * (1.f / C_);
            float var = rss[l] * (1.f / C_) - mu * mu;
            smu[l] = mu; srs[l] = rsqrtf(var + 1e-5f);
        }
        __syncthreads();
    }
    #pragma unroll
    for (int q = 0; q < 24; q++) {
        int e = tid + q * 256;
        int l = e / C_, c = e % C_;
        float v = (s[c * 17 + l] - smu[l]) * srs[l] * w[c] + bb[c];
        __nv_bfloat16 hi = __float2bfloat16(v);
        size_t idx = (size_t)(b * L_ + l0 + l) * C_ + c;
        g_xnh[idx] = hi;
        g_xnl[idx] = __float2bfloat16(v - __bfloat162float(hi));
    }
}

// ---------------- depthwise causal conv (k=4) + SiLU; fp32 + bf16 split, all (b*l,d) ----------------
__global__ void __launch_bounds__(256) conv_silu_kernel(const float* __restrict__ cw,
                                                        const float* __restrict__ cb) {
    __shared__ float s[67][36];
    __shared__ float sout[64][33];
    int l0 = blockIdx.x * 64, d0 = blockIdx.y * 32, b = blockIdx.z;
    int tid = threadIdx.x;
    for (int idx = tid; idx < 67 * 8; idx += 256) {
        int li = idx >> 3, d4 = idx & 7;
        int gl = l0 + li - 3;
        float4 v = make_float4(0.f, 0.f, 0.f, 0.f);
        if (gl >= 0) v = *(const float4*)(g_xi + ((size_t)(b*L_ + gl))*DIN + d0 + d4*4);
        *(float4*)&s[li][d4 * 4] = v;
    }
    __syncthreads();
    #pragma unroll
    for (int q = 0; q < 2; q++) {
        int item = tid + q * 256;
        int dd = item >> 4, lq = item & 15;
        int ll = lq * 4;
        int d = d0 + dd;
        float4 wv = *(const float4*)(cw + d * 4);
        float bias = cb[d];
        #pragma unroll
        for (int j = 0; j < 4; j++) {
            float acc = bias + wv.x * s[ll + j][dd] + wv.y * s[ll + j + 1][dd]
                             + wv.z * s[ll + j + 2][dd] + wv.w * s[ll + j + 3][dd];
            sout[ll + j][dd] = silu_f(acc);
        }
    }
    __syncthreads();
    #pragma unroll
    for (int q = 0; q < 8; q++) {
        int idx = tid + q * 256;
        int ll = idx >> 5, dd = idx & 31;
        float v = sout[ll][dd];
        __nv_bfloat16 hi = __float2bfloat16(v);
        size_t gi = (size_t)(b*L_ + l0 + ll)*DIN + d0 + dd;
        g_xlt[gi] = v;
        g_xch[gi] = hi;
        g_xcl[gi] = __float2bfloat16(v - __bfloat162float(hi));
    }
}

// ---------------- dt = softplus(x_dbl[:, :24] @ W_dt^T + b_dt) -> (b*l, d) ----------------
__global__ void dt_kernel(const float* __restrict__ Wdt, const float* __restrict__ bdt) {
    __shared__ float xs[32][25];
    __shared__ float ws[64][25];
    __shared__ float bs[64];
    int l0 = blockIdx.x * 32, d0 = blockIdx.y * 64, b = blockIdx.z;
    int tid = threadIdx.x;
    for (int idx = tid; idx < 32*24; idx += 256) {
        int ll = idx / 24, r = idx % 24;
        xs[ll][r] = g_xdbl[(size_t)(b*L_ + l0 + ll)*XW + r];
    }
    for (int idx = tid; idx < 64*24; idx += 256) {
        int dd = idx / 24, r = idx % 24;
        ws[dd][r] = Wdt[(size_t)(d0+dd)*DTR + r];
    }
    if (tid < 64) bs[tid] = bdt[d0 + tid];
    __syncthreads();
    #pragma unroll
    for (int t = 0; t < 8; t++) {
        int idx = tid + t*256;
        int dd = idx & 63, ll = idx >> 6;   // warp varies d -> coalesced (b*l,d) store
        float acc = bs[dd];
        #pragma unroll
        for (int r = 0; r < 24; r++) acc = fmaf(xs[ll][r], ws[dd][r], acc);
        float sp = (acc > 20.f) ? acc : log1pf(expf(acc));
        g_dtl[((size_t)(b*L_ + l0 + ll))*DIN + d0 + dd] = sp;
    }
}

// ---------------- scan v7: thread-per-channel, states in registers, no shfl ----------------
// Thread = (b, d, seg); all 16 states in registers. Warp = 32 consecutive d,
// same (b, seg): dt/x/z coalesced, B/C broadcast float4s.
// Grid (DIN/128, SEG, B_), block 128.

__device__ __forceinline__ void load_a16(const float* __restrict__ Alog, int d, float a[16]) {
    const float4* ap = (const float4*)(Alog + d * NST);
    #pragma unroll
    for (int q = 0; q < 4; q++) {
        float4 v = ap[q];
        a[4*q+0] = -__expf(v.x); a[4*q+1] = -__expf(v.y);
        a[4*q+2] = -__expf(v.z); a[4*q+3] = -__expf(v.w);
    }
}

// pass 1: per-segment F (final state from h=0) and G_n = exp(a_n * sum dt)
__global__ void __launch_bounds__(128) scan_pre_kernel(const float* __restrict__ Alog) {
    int d = blockIdx.x * 128 + threadIdx.x;
    int seg = blockIdx.y, b = blockIdx.z;
    float a[16];
    load_a16(Alog, d, a);
    float h[16];
    #pragma unroll
    for (int n = 0; n < 16; n++) h[n] = 0.f;
    float sdt = 0.f;
    for (int l = 0; l < SEGL; l++) {
        size_t base = (size_t)(b * L_ + seg * SEGL + l);
        float dt = g_dtl[base * DIN + d];
        float xv = g_xlt[base * DIN + d];
        const float4* bc4 = (const float4*)(g_xdbl + base * XW + DTR);
        float u = dt * xv;
        sdt += dt;
        #pragma unroll
        for (int q = 0; q < 4; q++) {
            float4 Bv = bc4[q];
            h[4*q+0] = fmaf(h[4*q+0], __expf(dt * a[4*q+0]), u * Bv.x);
            h[4*q+1] = fmaf(h[4*q+1], __expf(dt * a[4*q+1]), u * Bv.y);
            h[4*q+2] = fmaf(h[4*q+2], __expf(dt * a[4*q+2]), u * Bv.z);
            h[4*q+3] = fmaf(h[4*q+3], __expf(dt * a[4*q+3]), u * Bv.w);
        }
    }
    size_t off = ((size_t)(b * DIN + d) * SEG + seg) * NST;
    float4* F4 = (float4*)(g_segF + off);
    float4* G4 = (float4*)(g_segG + off);
    #pragma unroll
    for (int q = 0; q < 4; q++) {
        F4[q] = make_float4(h[4*q], h[4*q+1], h[4*q+2], h[4*q+3]);
        G4[q] = make_float4(__expf(sdt * a[4*q+0]), __expf(sdt * a[4*q+1]),
                            __expf(sdt * a[4*q+2]), __expf(sdt * a[4*q+3]));
    }
}

// pass 2: sequential combine of segment summaries -> entry state per segment
__global__ void scan_mid_kernel() {
    int i = blockIdx.x * 256 + threadIdx.x;          // (b*DIN+d)*NST+n
    if (i >= B_ * DIN * NST) return;
    size_t base = (size_t)(i / NST) * SEG * NST + (i % NST);
    float h = 0.f;
    #pragma unroll
    for (int s = 0; s < SEG; s++) {
        size_t o = base + (size_t)s * NST;
        g_segH[o] = h;
        h = g_segF[o] + g_segG[o] * h;
    }
}

// pass 3: full scan from entry state; fuses y*silu(z) gate + bf16 split output
__global__ void __launch_bounds__(128) scan_kernel(const float* __restrict__ Alog,
                                                   const float* __restrict__ Dp) {
    int d = blockIdx.x * 128 + threadIdx.x;
    int seg = blockIdx.y, b = blockIdx.z;
    float a[16];
    load_a16(Alog, d, a);
    float Dd = Dp[d];
    float h[16];
    {
        const float4* H4 = (const float4*)(g_segH + ((size_t)(b * DIN + d) * SEG + seg) * NST);
        #pragma unroll
        for (int q = 0; q < 4; q++) {
            float4 v = H4[q];
            h[4*q] = v.x; h[4*q+1] = v.y; h[4*q+2] = v.z; h[4*q+3] = v.w;
        }
    }
    for (int l = 0; l < SEGL; l++) {
        size_t base = (size_t)(b * L_ + seg * SEGL + l);
        float dt = g_dtl[base * DIN + d];
        float xv = g_xlt[base * DIN + d];
        const float4* bc4 = (const float4*)(g_xdbl + base * XW + DTR);
        float u = dt * xv;
        float y0 = 0.f, y1 = 0.f, y2 = 0.f, y3 = 0.f;
        #pragma unroll
        for (int q = 0; q < 4; q++) {
            float4 Bv = bc4[q];
            float4 Cv = bc4[4 + q];
            h[4*q+0] = fmaf(h[4*q+0], __expf(dt * a[4*q+0]), u * Bv.x);
            y0 = fmaf(h[4*q+0], Cv.x, y0);
            h[4*q+1] = fmaf(h[4*q+1], __expf(dt * a[4*q+1]), u * Bv.y);
            y1 = fmaf(h[4*q+1], Cv.y, y1);
            h[4*q+2] = fmaf(h[4*q+2], __expf(dt * a[4*q+2]), u * Bv.z);
            y2 = fmaf(h[4*q+2], Cv.z, y2);
            h[4*q+3] = fmaf(h[4*q+3], __expf(dt * a[4*q+3]), u * Bv.w);
            y3 = fmaf(h[4*q+3], Cv.w, y3);
        }
        float y = ((y0 + y1) + (y2 + y3)) + xv * Dd;
        float zv = g_z[base * DIN + d];
        float gv = y * silu_f(zv);
        __nv_bfloat16 hi = __float2bfloat16(gv);
        g_gh[base * DIN + d] = hi;
        g_gl[base * DIN + d] = __float2bfloat16(gv - __bfloat162float(hi));
    }
}

// ---------------- launch ----------------
// Diagnostic: pass-3 also at slot 4 (deterministic across replays; its g_gh/g_gl
// output is overwritten by the real pass-3 after pre/mid recompute seg states).
extern "C" void kernel_launch(void* const* d_in, const int* in_sizes, int n_in,
                              void* d_out, int out_size) {
    const float* x      = (const float*)d_in[0];
    const float* ln_w   = (const float*)d_in[1];
    const float* ln_b   = (const float*)d_in[2];
    const float* W_in   = (const float*)d_in[3];
    const float* conv_w = (const float*)d_in[4];
    const float* conv_b = (const float*)d_in[5];
    const float* W_xprj = (const float*)d_in[6];
    const float* W_dt   = (const float*)d_in[7];
    const float* b_dt   = (const float*)d_in[8];
    const float* A_log  = (const float*)d_in[9];
    const float* Dp     = (const float*)d_in[10];
    const float* W_out  = (const float*)d_in[11];
    float* out = (float*)d_out;

    static int smem_set = 0;
    if (!smem_set) {
        cudaFuncSetAttribute(hmma_gemm_in_kernel,  cudaFuncAttributeMaxDynamicSharedMemorySize, SMEM_HMMA);
        cudaFuncSetAttribute(hmma_gemm_out_kernel, cudaFuncAttributeMaxDynamicSharedMemorySize, SMEM_HMMA);
        cudaFuncSetAttribute(hmma_xproj_kernel,    cudaFuncAttributeMaxDynamicSharedMemorySize, SMEM_X);
        smem_set = 1;
    }

    dim3 scan_grid(DIN/128, SEG, B_);

    cvt_w1_kernel<<<(N_WIN + 255)/256, 256>>>(W_in);                       // 1
    cvt_w2_kernel<<<(N_WOUT + N_WX + 255)/256, 256>>>(W_out, W_xprj);      // 2
    ln_fused_kernel<<<dim3(L_/16, B_), 256>>>(x, ln_w, ln_b);              // 3
    scan_kernel<<<scan_grid, 128>>>(A_log, Dp);                            // 4 <- ncu slot (diagnostic)
    hmma_gemm_in_kernel<<<dim3((2*DIN)/128, (B_*L_)/128), 256, SMEM_HMMA>>>();
    conv_silu_kernel<<<dim3(L_/64, DIN/32, B_), 256>>>(conv_w, conv_b);
    hmma_xproj_kernel<<<(B_*L_)/128, 256, SMEM_X>>>();
    dt_kernel<<<dim3(L_/32, DIN/64, B_), 256>>>(W_dt, b_dt);
    scan_pre_kernel<<<scan_grid, 128>>>(A_log);
    scan_mid_kernel<<<(B_*DIN*NST + 255)/256, 256>>>();
    scan_kernel<<<scan_grid, 128>>>(A_log, Dp);                            // real pass 3
    hmma_gemm_out_kernel<<<dim3((B_*L_)/128, C_/128), 256, SMEM_HMMA>>>(out);
}

// round 16
// speedup vs baseline: 2.4598x; 2.4598x over previous
#include <cuda_runtime.h>
#include <cuda_bf16.h>
#include <cstdint>

#define B_   2
#define C_   384
#define L_   8192
#define DIN  768
#define NST  16
#define DTR  24
#define XW   56        // dt_rank + 2*d_state
#define XWP  64        // padded rows of W_xproj for HMMA
#define SEG  128
#define SEGL (L_/SEG)  // 64

// ---------------- scratch (device globals; no allocation allowed) ----------------
__device__ float g_xi  [(size_t)B_*L_*DIN];    // (b*l, d)
__device__ float g_z   [(size_t)B_*L_*DIN];    // (b*l, d)
__device__ float g_xlt [(size_t)B_*L_*DIN];    // (b*l, d)  conv+silu output fp32 (scan)
__device__ float g_xdbl[(size_t)B_*L_*XW];     // (b*l, 56)
__device__ float g_dtl [(size_t)B_*L_*DIN];    // (b*l, d)  softplus(dt)
__device__ float g_segF[(size_t)B_*DIN*SEG*NST];   // segment final state (h0=0)
__device__ float g_segG[(size_t)B_*DIN*SEG*NST];   // segment decay
__device__ float g_segH[(size_t)B_*DIN*SEG*NST];   // segment entry state

// bf16 split operands for tensor-core GEMMs
__device__ __nv_bfloat16 g_xnh[(size_t)B_*L_*C_], g_xnl[(size_t)B_*L_*C_];       // xn   (b*l, c)
__device__ __nv_bfloat16 g_winh[(size_t)2*DIN*C_], g_winl[(size_t)2*DIN*C_];     // W_in
__device__ __nv_bfloat16 g_xch[(size_t)B_*L_*DIN], g_xcl[(size_t)B_*L_*DIN];     // xc   (b*l, d)
__device__ __nv_bfloat16 g_wxh[(size_t)XWP*DIN], g_wxl[(size_t)XWP*DIN];         // W_xproj padded
__device__ __nv_bfloat16 g_gh [(size_t)B_*L_*DIN], g_gl [(size_t)B_*L_*DIN];     // y*silu(z)
__device__ __nv_bfloat16 g_wouth[(size_t)C_*DIN], g_woutl[(size_t)C_*DIN];       // W_out

__device__ __forceinline__ float silu_f(float v) {
    return v * (1.f / (1.f + __expf(-v)));
}
__device__ __forceinline__ uint32_t smem_u32(const void* p) {
    uint32_t a;
    asm("{ .reg .u64 t; cvta.to.shared.u64 t, %1; cvt.u32.u64 %0, t; }" : "=r"(a) : "l"(p));
    return a;
}

// ================= async-copy / HMMA building blocks (base sm_103 legal) =================
#define CP16(dst, src) \
    asm volatile("cp.async.cg.shared.global [%0], [%1], 16;" :: "r"(dst), "l"(src))
#define CP_COMMIT() asm volatile("cp.async.commit_group;" ::: "memory")
#define CP_WAIT1()  asm volatile("cp.async.wait_group 1;" ::: "memory")
#define CP_WAIT0()  asm volatile("cp.async.wait_group 0;" ::: "memory")

__device__ __forceinline__ void ldsm4(uint32_t r[4], uint32_t addr) {
    asm volatile("ldmatrix.sync.aligned.m8n8.x4.shared.b16 {%0,%1,%2,%3}, [%4];"
        : "=r"(r[0]), "=r"(r[1]), "=r"(r[2]), "=r"(r[3]) : "r"(addr));
}
__device__ __forceinline__ void mma16816(float d[4], const uint32_t a[4],
                                         uint32_t b0, uint32_t b1) {
    asm volatile("mma.sync.aligned.m16n8k16.row.col.f32.bf16.bf16.f32 "
        "{%0,%1,%2,%3}, {%4,%5,%6,%7}, {%8,%9}, {%0,%1,%2,%3};"
        : "+f"(d[0]), "+f"(d[1]), "+f"(d[2]), "+f"(d[3])
        : "r"(a[0]), "r"(a[1]), "r"(a[2]), "r"(a[3]), "r"(b0), "r"(b1));
}

// ---------- 128x128 mainloop: 3-stage cp.async pipeline, one barrier per chunk ----------
__device__ __forceinline__ void stage_chunk(uint32_t sbuf,
        const __nv_bfloat16* __restrict__ Ah, const __nv_bfloat16* __restrict__ Al,
        int arow0, int lda,
        const __nv_bfloat16* __restrict__ Bh, const __nv_bfloat16* __restrict__ Bl,
        int brow0, int ldb, int kc, int tid) {
    const __nv_bfloat16* srcs[4] = {Ah, Al, Bh, Bl};
    #pragma unroll
    for (int tile = 0; tile < 4; tile++) {
        const __nv_bfloat16* src = srcs[tile];
        int ld = (tile < 2) ? lda : ldb;
        int r0 = (tile < 2) ? arow0 : brow0;
        #pragma unroll
        for (int h = 0; h < 2; h++) {
            int cid = tid + h * 256;
            int row = cid >> 2, ch = cid & 3;
            const void* g = src + (size_t)(r0 + row) * ld + kc * 32 + ch * 8;
            uint32_t d = sbuf + tile * 8192 + row * 64 + ((ch ^ ((row >> 1) & 3)) << 4);
            CP16(d, g);
        }
    }
}
__device__ __forceinline__ void compute_chunk(uint32_t sbuf, int warp_m, int warp_n,
                                              int lane, float acc[4][4][4]) {
    int arow = lane & 15;
    int akc  = lane >> 4;
    int bro  = (lane & 7) + ((lane >> 4) << 3);
    int bkc  = (lane >> 3) & 1;
    #pragma unroll
    for (int k16 = 0; k16 < 2; k16++) {
        uint32_t ah[4][4], al[4][4], bhf[2][4], blf[2][4];
        #pragma unroll
        for (int mi = 0; mi < 4; mi++) {
            int row = warp_m * 64 + mi * 16 + arow;
            int ch = k16 * 2 + akc;
            uint32_t off = row * 64 + ((ch ^ ((row >> 1) & 3)) << 4);
            ldsm4(ah[mi], sbuf + off);
            ldsm4(al[mi], sbuf + 8192 + off);
        }
        #pragma unroll
        for (int p = 0; p < 2; p++) {
            int row = warp_n * 32 + p * 16 + bro;
            int ch = k16 * 2 + bkc;
            uint32_t off = row * 64 + ((ch ^ ((row >> 1) & 3)) << 4);
            ldsm4(bhf[p], sbuf + 16384 + off);
            ldsm4(blf[p], sbuf + 24576 + off);
        }
        #pragma unroll
        for (int mi = 0; mi < 4; mi++)
            #pragma unroll
            for (int nj = 0; nj < 4; nj++) {
                int p = nj >> 1, w = (nj & 1) * 2;
                mma16816(acc[mi][nj], ah[mi], bhf[p][w], bhf[p][w + 1]);
                mma16816(acc[mi][nj], ah[mi], blf[p][w], blf[p][w + 1]);
                mma16816(acc[mi][nj], al[mi], bhf[p][w], bhf[p][w + 1]);
            }
    }
}
__device__ __forceinline__ void mma_mainloop(char* smem, int tid,
        const __nv_bfloat16* Ah, const __nv_bfloat16* Al, int arow0, int lda,
        const __nv_bfloat16* Bh, const __nv_bfloat16* Bl, int brow0, int ldb,
        int nch, float acc[4][4][4]) {
    uint32_t sb = smem_u32(smem);
    int warp_m = (tid >> 5) >> 2, warp_n = (tid >> 5) & 3, lane = tid & 31;
    #pragma unroll
    for (int mi = 0; mi < 4; mi++)
        #pragma unroll
        for (int nj = 0; nj < 4; nj++)
            #pragma unroll
            for (int r = 0; r < 4; r++) acc[mi][nj][r] = 0.f;
    stage_chunk(sb, Ah, Al, arow0, lda, Bh, Bl, brow0, ldb, 0, tid);
    CP_COMMIT();
    stage_chunk(sb + 32768, Ah, Al, arow0, lda, Bh, Bl, brow0, ldb, 1, tid);
    CP_COMMIT();
    for (int c = 0; c < nch; c++) {
        if (c + 1 < nch) CP_WAIT1(); else CP_WAIT0();
        __syncthreads();
        compute_chunk(sb + (c % 3) * 32768, warp_m, warp_n, lane, acc);
        if (c + 2 < nch) {
            stage_chunk(sb + ((c + 2) % 3) * 32768, Ah, Al, arow0, lda,
                        Bh, Bl, brow0, ldb, c + 2, tid);
            CP_COMMIT();
        }
    }
}
#define SMEM_HMMA (3 * 32768)

// ---------- 128x64 mainloop for xproj (2-stage, proven) ----------
__device__ __forceinline__ void stage_chunk_x(uint32_t sbuf, int kc, int arow0, int tid) {
    #pragma unroll
    for (int h = 0; h < 2; h++) {
        int cid = tid + h * 256;
        int row = cid >> 2, ch = cid & 3;
        const void* gh_ = g_xch + (size_t)(arow0 + row) * DIN + kc * 32 + ch * 8;
        const void* gl_ = g_xcl + (size_t)(arow0 + row) * DIN + kc * 32 + ch * 8;
        uint32_t off = row * 64 + ((ch ^ ((row >> 1) & 3)) << 4);
        CP16(sbuf + off, gh_);
        CP16(sbuf + 8192 + off, gl_);
    }
    {
        int row = tid >> 2, ch = tid & 3;
        const void* gh_ = g_wxh + (size_t)row * DIN + kc * 32 + ch * 8;
        const void* gl_ = g_wxl + (size_t)row * DIN + kc * 32 + ch * 8;
        uint32_t off = row * 64 + ((ch ^ ((row >> 1) & 3)) << 4);
        CP16(sbuf + 16384 + off, gh_);
        CP16(sbuf + 20480 + off, gl_);
    }
}
__device__ __forceinline__ void compute_chunk_x(uint32_t sbuf, int warp_m, int warp_n,
                                                int lane, float acc[2][4][4]) {
    int arow = lane & 15;
    int akc  = lane >> 4;
    int bro  = (lane & 7) + ((lane >> 4) << 3);
    int bkc  = (lane >> 3) & 1;
    #pragma unroll
    for (int k16 = 0; k16 < 2; k16++) {
        uint32_t ah[2][4], al[2][4], bhf[2][4], blf[2][4];
        #pragma unroll
        for (int mi = 0; mi < 2; mi++) {
            int row = warp_m * 32 + mi * 16 + arow;
            int ch = k16 * 2 + akc;
            uint32_t off = row * 64 + ((ch ^ ((row >> 1) & 3)) << 4);
            ldsm4(ah[mi], sbuf + off);
            ldsm4(al[mi], sbuf + 8192 + off);
        }
        #pragma unroll
        for (int p = 0; p < 2; p++) {
            int row = warp_n * 32 + p * 16 + bro;
            int ch = k16 * 2 + bkc;
            uint32_t off = row * 64 + ((ch ^ ((row >> 1) & 3)) << 4);
            ldsm4(bhf[p], sbuf + 16384 + off);
            ldsm4(blf[p], sbuf + 20480 + off);
        }
        #pragma unroll
        for (int mi = 0; mi < 2; mi++)
            #pragma unroll
            for (int nj = 0; nj < 4; nj++) {
                int p = nj >> 1, w = (nj & 1) * 2;
                mma16816(acc[mi][nj], ah[mi], bhf[p][w], bhf[p][w + 1]);
                mma16816(acc[mi][nj], ah[mi], blf[p][w], blf[p][w + 1]);
                mma16816(acc[mi][nj], al[mi], bhf[p][w], bhf[p][w + 1]);
            }
    }
}
#define SMEM_X (2 * 24576)

__global__ void __launch_bounds__(256) hmma_xproj_kernel() {
    extern __shared__ char smem[];
    uint32_t sb = smem_u32(smem);
    int tid = threadIdx.x;
    int bm = blockIdx.x;
    int arow0 = bm * 128;
    int warp = tid >> 5, lane = tid & 31;
    int warp_m = warp >> 1, warp_n = warp & 1;
    float acc[2][4][4];
    #pragma unroll
    for (int mi = 0; mi < 2; mi++)
        #pragma unroll
        for (int nj = 0; nj < 4; nj++)
            #pragma unroll
            for (int r = 0; r < 4; r++) acc[mi][nj][r] = 0.f;
    stage_chunk_x(sb, 0, arow0, tid);
    CP_COMMIT();
    const int nch = DIN / 32;
    for (int c = 0; c < nch; c++) {
        if (c + 1 < nch) {
            stage_chunk_x(sb + ((c + 1) & 1) * 24576, c + 1, arow0, tid);
            CP_COMMIT();
            CP_WAIT1();
        } else {
            CP_WAIT0();
        }
        __syncthreads();
        compute_chunk_x(sb + (c & 1) * 24576, warp_m, warp_n, lane, acc);
        __syncthreads();
    }
    int g = lane >> 2, t = lane & 3;
    #pragma unroll
    for (int mi = 0; mi < 2; mi++) {
        int row = arow0 + warp_m * 32 + mi * 16 + g;
        #pragma unroll
        for (int nj = 0; nj < 4; nj++) {
            int col = warp_n * 32 + nj * 8 + 2 * t;
            if (col < XW) {
                *(float2*)(g_xdbl + (size_t)row * XW + col)       = make_float2(acc[mi][nj][0], acc[mi][nj][1]);
                *(float2*)(g_xdbl + (size_t)(row + 8) * XW + col) = make_float2(acc[mi][nj][2], acc[mi][nj][3]);
            }
        }
    }
}

// ---------------- tensor GEMM 1: xz = xn @ W_in^T -> g_xi / g_z ----------------
__global__ void __launch_bounds__(256) hmma_gemm_in_kernel() {
    extern __shared__ char smem[];
    int tid = threadIdx.x;
    int bn = blockIdx.x, bm = blockIdx.y;
    float acc[4][4][4];
    mma_mainloop(smem, tid, g_xnh, g_xnl, bm * 128, C_,
                 g_winh, g_winl, bn * 128, C_, C_ / 32, acc);
    int warp_m = (tid >> 5) >> 2, warp_n = (tid >> 5) & 3, lane = tid & 31;
    int g = lane >> 2, t = lane & 3;
    int col0 = bn * 128;
    float* dst = (col0 < DIN) ? g_xi : g_z;
    int cbase = ((col0 < DIN) ? col0 : col0 - DIN) + warp_n * 32;
    #pragma unroll
    for (int mi = 0; mi < 4; mi++) {
        int row = bm * 128 + warp_m * 64 + mi * 16 + g;
        #pragma unroll
        for (int nj = 0; nj < 4; nj++) {
            int col = cbase + nj * 8 + 2 * t;
            *(float2*)(dst + (size_t)row * DIN + col)       = make_float2(acc[mi][nj][0], acc[mi][nj][1]);
            *(float2*)(dst + (size_t)(row + 8) * DIN + col) = make_float2(acc[mi][nj][2], acc[mi][nj][3]);
        }
    }
}

// ---------------- tensor GEMM 2: out = W_out x gate^T, store (b,c,l) ----------------
__global__ void __launch_bounds__(256) hmma_gemm_out_kernel(float* __restrict__ out) {
    extern __shared__ char smem[];
    int tid = threadIdx.x;
    int bn = blockIdx.x, bm = blockIdx.y;
    float acc[4][4][4];
    mma_mainloop(smem, tid, g_wouth, g_woutl, bm * 128, DIN,
                 g_gh, g_gl, bn * 128, DIN, DIN / 32, acc);
    int warp_m = (tid >> 5) >> 2, warp_n = (tid >> 5) & 3, lane = tid & 31;
    int g = lane >> 2, t = lane & 3;
    int nrow0 = bn * 128 + warp_n * 32;
    int b = nrow0 / L_;
    #pragma unroll
    for (int mi = 0; mi < 4; mi++) {
        int c = bm * 128 + warp_m * 64 + mi * 16 + g;
        #pragma unroll
        for (int nj = 0; nj < 4; nj++) {
            int l = (nrow0 % L_) + nj * 8 + 2 * t;
            *(float2*)(out + ((size_t)(b * C_ + c)) * L_ + l)     = make_float2(acc[mi][nj][0], acc[mi][nj][1]);
            *(float2*)(out + ((size_t)(b * C_ + c + 8)) * L_ + l) = make_float2(acc[mi][nj][2], acc[mi][nj][3]);
        }
    }
}

// ---------------- weight splits ----------------
#define N_WIN  (2*DIN*C_)
#define N_WOUT (C_*DIN)
#define N_WX   (XWP*DIN)
__global__ void cvt_w1_kernel(const float* __restrict__ W_in) {
    int i = blockIdx.x * 256 + threadIdx.x;
    if (i >= N_WIN) return;
    float v = W_in[i];
    __nv_bfloat16 hi = __float2bfloat16(v);
    g_winh[i] = hi;
    g_winl[i] = __float2bfloat16(v - __bfloat162float(hi));
}
__global__ void cvt_w2_kernel(const float* __restrict__ W_out, const float* __restrict__ Wx) {
    int i = blockIdx.x * 256 + threadIdx.x;
    float v; __nv_bfloat16 *h, *l; int j;
    if (i < N_WOUT) {
        j = i; v = W_out[j]; h = g_wouth; l = g_woutl;
    } else if (i < N_WOUT + N_WX) {
        j = i - N_WOUT;
        int r = j / DIN;
        v = (r < XW) ? Wx[(size_t)r * DIN + (j % DIN)] : 0.f;
        h = g_wxh; l = g_wxl;
    } else return;
    __nv_bfloat16 hi = __float2bfloat16(v);
    h[j] = hi;
    l[j] = __float2bfloat16(v - __bfloat162float(hi));
}

// ---------------- fused LayerNorm: stats + apply + transpose + bf16 split ----------------
__global__ void __launch_bounds__(256) ln_fused_kernel(const float* __restrict__ x,
        const float* __restrict__ w, const float* __restrict__ bb) {
    __shared__ float s[C_ * 17];          // [c][l] stride 17
    __shared__ float rs_[256], rss[256];
    __shared__ float smu[16], srs[16];
    int l0 = blockIdx.x * 16, b = blockIdx.y;
    int tid = threadIdx.x;
    #pragma unroll
    for (int q = 0; q < 6; q++) {
        int id = tid + q * 256;
        int c = id >> 2, j = id & 3;
        float4 v = *(const float4*)(x + ((size_t)(b * C_ + c)) * L_ + l0 + j * 4);
        float* p = s + c * 17 + j * 4;
        p[0] = v.x; p[1] = v.y; p[2] = v.z; p[3] = v.w;
    }
    __syncthreads();
    {
        int l = tid & 15, gr = tid >> 4;
        float sum = 0.f, ss = 0.f;
        for (int c = gr; c < C_; c += 16) {
            float v = s[c * 17 + l];
            sum += v; ss += v * v;
        }
        rs_[tid] = sum; rss[tid] = ss;
        __syncthreads();
        #pragma unroll
        for (int off = 8; off > 0; off >>= 1) {
            if (gr < off) { rs_[tid] += rs_[tid + off * 16]; rss[tid] += rss[tid + off * 16]; }
            __syncthreads();
        }
        if (gr == 0) {
            float mu = rs_[l] * (1.f / C_);
            float var = rss[l] * (1.f / C_) - mu * mu;
            smu[l] = mu; srs[l] = rsqrtf(var + 1e-5f);
        }
        __syncthreads();
    }
    #pragma unroll
    for (int q = 0; q < 24; q++) {
        int e = tid + q * 256;
        int l = e / C_, c = e % C_;
        float v = (s[c * 17 + l] - smu[l]) * srs[l] * w[c] + bb[c];
        __nv_bfloat16 hi = __float2bfloat16(v);
        size_t idx = (size_t)(b * L_ + l0 + l) * C_ + c;
        g_xnh[idx] = hi;
        g_xnl[idx] = __float2bfloat16(v - __bfloat162float(hi));
    }
}

// ---------------- depthwise causal conv (k=4) + SiLU; fp32 + bf16 split, all (b*l,d) ----------------
__global__ void __launch_bounds__(256) conv_silu_kernel(const float* __restrict__ cw,
                                                        const float* __restrict__ cb) {
    __shared__ float s[67][36];
    __shared__ float sout[64][33];
    int l0 = blockIdx.x * 64, d0 = blockIdx.y * 32, b = blockIdx.z;
    int tid = threadIdx.x;
    for (int idx = tid; idx < 67 * 8; idx += 256) {
        int li = idx >> 3, d4 = idx & 7;
        int gl = l0 + li - 3;
        float4 v = make_float4(0.f, 0.f, 0.f, 0.f);
        if (gl >= 0) v = *(const float4*)(g_xi + ((size_t)(b*L_ + gl))*DIN + d0 + d4*4);
        *(float4*)&s[li][d4 * 4] = v;
    }
    __syncthreads();
    #pragma unroll
    for (int q = 0; q < 2; q++) {
        int item = tid + q * 256;
        int dd = item >> 4, lq = item & 15;
        int ll = lq * 4;
        int d = d0 + dd;
        float4 wv = *(const float4*)(cw + d * 4);
        float bias = cb[d];
        #pragma unroll
        for (int j = 0; j < 4; j++) {
            float acc = bias + wv.x * s[ll + j][dd] + wv.y * s[ll + j + 1][dd]
                             + wv.z * s[ll + j + 2][dd] + wv.w * s[ll + j + 3][dd];
            sout[ll + j][dd] = silu_f(acc);
        }
    }
    __syncthreads();
    #pragma unroll
    for (int q = 0; q < 8; q++) {
        int idx = tid + q * 256;
        int ll = idx >> 5, dd = idx & 31;
        float v = sout[ll][dd];
        __nv_bfloat16 hi = __float2bfloat16(v);
        size_t gi = (size_t)(b*L_ + l0 + ll)*DIN + d0 + dd;
        g_xlt[gi] = v;
        g_xch[gi] = hi;
        g_xcl[gi] = __float2bfloat16(v - __bfloat162float(hi));
    }
}

// ---------------- dt = softplus(x_dbl[:, :24] @ W_dt^T + b_dt) -> (b*l, d) ----------------
__global__ void dt_kernel(const float* __restrict__ Wdt, const float* __restrict__ bdt) {
    __shared__ float xs[32][25];
    __shared__ float ws[64][25];
    __shared__ float bs[64];
    int l0 = blockIdx.x * 32, d0 = blockIdx.y * 64, b = blockIdx.z;
    int tid = threadIdx.x;
    for (int idx = tid; idx < 32*24; idx += 256) {
        int ll = idx / 24, r = idx % 24;
        xs[ll][r] = g_xdbl[(size_t)(b*L_ + l0 + ll)*XW + r];
    }
    for (int idx = tid; idx < 64*24; idx += 256) {
        int dd = idx / 24, r = idx % 24;
        ws[dd][r] = Wdt[(size_t)(d0+dd)*DTR + r];
    }
    if (tid < 64) bs[tid] = bdt[d0 + tid];
    __syncthreads();
    #pragma unroll
    for (int t = 0; t < 8; t++) {
        int idx = tid + t*256;
        int dd = idx & 63, ll = idx >> 6;   // warp varies d -> coalesced (b*l,d) store
        float acc = bs[dd];
        #pragma unroll
        for (int r = 0; r < 24; r++) acc = fmaf(xs[ll][r], ws[dd][r], acc);
        float sp = (acc > 20.f) ? acc : log1pf(expf(acc));
        g_dtl[((size_t)(b*L_ + l0 + ll))*DIN + d0 + dd] = sp;
    }
}

// ---------------- scan v8: thread-per-(d,seg), SEG=128 -> 6144 warps ----------------
// Thread = (b, d, seg); all 16 states in registers. Warp = 32 consecutive d,
// same (b, seg): dt/x/z coalesced, B/C broadcast float4s.
// Grid (DIN/128, SEG, B_) = 1536 blocks of 128.

__device__ __forceinline__ void load_a16(const float* __restrict__ Alog, int d, float a[16]) {
    const float4* ap = (const float4*)(Alog + d * NST);
    #pragma unroll
    for (int q = 0; q < 4; q++) {
        float4 v = ap[q];
        a[4*q+0] = -__expf(v.x); a[4*q+1] = -__expf(v.y);
        a[4*q+2] = -__expf(v.z); a[4*q+3] = -__expf(v.w);
    }
}

// pass 1: per-segment F (final state from h=0) and G_n = exp(a_n * sum dt)
__global__ void __launch_bounds__(128) scan_pre_kernel(const float* __restrict__ Alog) {
    int d = blockIdx.x * 128 + threadIdx.x;
    int seg = blockIdx.y, b = blockIdx.z;
    float a[16];
    load_a16(Alog, d, a);
    float h[16];
    #pragma unroll
    for (int n = 0; n < 16; n++) h[n] = 0.f;
    float sdt = 0.f;
    #pragma unroll 2
    for (int l = 0; l < SEGL; l++) {
        size_t base = (size_t)(b * L_ + seg * SEGL + l);
        float dt = g_dtl[base * DIN + d];
        float xv = g_xlt[base * DIN + d];
        const float4* bc4 = (const float4*)(g_xdbl + base * XW + DTR);
        float u = dt * xv;
        sdt += dt;
        #pragma unroll
        for (int q = 0; q < 4; q++) {
            float4 Bv = bc4[q];
            h[4*q+0] = fmaf(h[4*q+0], __expf(dt * a[4*q+0]), u * Bv.x);
            h[4*q+1] = fmaf(h[4*q+1], __expf(dt * a[4*q+1]), u * Bv.y);
            h[4*q+2] = fmaf(h[4*q+2], __expf(dt * a[4*q+2]), u * Bv.z);
            h[4*q+3] = fmaf(h[4*q+3], __expf(dt * a[4*q+3]), u * Bv.w);
        }
    }
    size_t off = ((size_t)(b * DIN + d) * SEG + seg) * NST;
    float4* F4 = (float4*)(g_segF + off);
    float4* G4 = (float4*)(g_segG + off);
    #pragma unroll
    for (int q = 0; q < 4; q++) {
        F4[q] = make_float4(h[4*q], h[4*q+1], h[4*q+2], h[4*q+3]);
        G4[q] = make_float4(__expf(sdt * a[4*q+0]), __expf(sdt * a[4*q+1]),
                            __expf(sdt * a[4*q+2]), __expf(sdt * a[4*q+3]));
    }
}

// pass 2: sequential combine of segment summaries -> entry state per segment
__global__ void scan_mid_kernel() {
    int i = blockIdx.x * 256 + threadIdx.x;          // (b*DIN+d)*NST+n
    if (i >= B_ * DIN * NST) return;
    size_t base = (size_t)(i / NST) * SEG * NST + (i % NST);
    float h = 0.f;
    #pragma unroll 8
    for (int s = 0; s < SEG; s++) {
        size_t o = base + (size_t)s * NST;
        g_segH[o] = h;
        h = g_segF[o] + g_segG[o] * h;
    }
}

// pass 3: full scan from entry state; fuses y*silu(z) gate + bf16 split output
__global__ void __launch_bounds__(128) scan_kernel(const float* __restrict__ Alog,
                                                   const float* __restrict__ Dp) {
    int d = blockIdx.x * 128 + threadIdx.x;
    int seg = blockIdx.y, b = blockIdx.z;
    float a[16];
    load_a16(Alog, d, a);
    float Dd = Dp[d];
    float h[16];
    {
        const float4* H4 = (const float4*)(g_segH + ((size_t)(b * DIN + d) * SEG + seg) * NST);
        #pragma unroll
        for (int q = 0; q < 4; q++) {
            float4 v = H4[q];
            h[4*q] = v.x; h[4*q+1] = v.y; h[4*q+2] = v.z; h[4*q+3] = v.w;
        }
    }
    #pragma unroll 2
    for (int l = 0; l < SEGL; l++) {
        size_t base = (size_t)(b * L_ + seg * SEGL + l);
        float dt = g_dtl[base * DIN + d];
        float xv = g_xlt[base * DIN + d];
        const float4* bc4 = (const float4*)(g_xdbl + base * XW + DTR);
        float u = dt * xv;
        float y0 = 0.f, y1 = 0.f, y2 = 0.f, y3 = 0.f;
        #pragma unroll
        for (int q = 0; q < 4; q++) {
            float4 Bv = bc4[q];
            float4 Cv = bc4[4 + q];
            h[4*q+0] = fmaf(h[4*q+0], __expf(dt * a[4*q+0]), u * Bv.x);
            y0 = fmaf(h[4*q+0], Cv.x, y0);
            h[4*q+1] = fmaf(h[4*q+1], __expf(dt * a[4*q+1]), u * Bv.y);
            y1 = fmaf(h[4*q+1], Cv.y, y1);
            h[4*q+2] = fmaf(h[4*q+2], __expf(dt * a[4*q+2]), u * Bv.z);
            y2 = fmaf(h[4*q+2], Cv.z, y2);
            h[4*q+3] = fmaf(h[4*q+3], __expf(dt * a[4*q+3]), u * Bv.w);
            y3 = fmaf(h[4*q+3], Cv.w, y3);
        }
        float y = ((y0 + y1) + (y2 + y3)) + xv * Dd;
        float zv = g_z[base * DIN + d];
        float gv = y * silu_f(zv);
        __nv_bfloat16 hi = __float2bfloat16(gv);
        g_gh[base * DIN + d] = hi;
        g_gl[base * DIN + d] = __float2bfloat16(gv - __bfloat162float(hi));
    }
}

// ---------------- launch ----------------
// Diagnostic: pass-3 also at slot 4 (deterministic across replays; its g_gh/g_gl
// output is overwritten by the real pass-3 after pre/mid recompute seg states).
extern "C" void kernel_launch(void* const* d_in, const int* in_sizes, int n_in,
                              void* d_out, int out_size) {
    const float* x      = (const float*)d_in[0];
    const float* ln_w   = (const float*)d_in[1];
    const float* ln_b   = (const float*)d_in[2];
    const float* W_in   = (const float*)d_in[3];
    const float* conv_w = (const float*)d_in[4];
    const float* conv_b = (const float*)d_in[5];
    const float* W_xprj = (const float*)d_in[6];
    const float* W_dt   = (const float*)d_in[7];
    const float* b_dt   = (const float*)d_in[8];
    const float* A_log  = (const float*)d_in[9];
    const float* Dp     = (const float*)d_in[10];
    const float* W_out  = (const float*)d_in[11];
    float* out = (float*)d_out;

    static int smem_set = 0;
    if (!smem_set) {
        cudaFuncSetAttribute(hmma_gemm_in_kernel,  cudaFuncAttributeMaxDynamicSharedMemorySize, SMEM_HMMA);
        cudaFuncSetAttribute(hmma_gemm_out_kernel, cudaFuncAttributeMaxDynamicSharedMemorySize, SMEM_HMMA);
        cudaFuncSetAttribute(hmma_xproj_kernel,    cudaFuncAttributeMaxDynamicSharedMemorySize, SMEM_X);
        smem_set = 1;
    }

    dim3 scan_grid(DIN/128, SEG, B_);

    cvt_w1_kernel<<<(N_WIN + 255)/256, 256>>>(W_in);                       // 1
    cvt_w2_kernel<<<(N_WOUT + N_WX + 255)/256, 256>>>(W_out, W_xprj);      // 2
    ln_fused_kernel<<<dim3(L_/16, B_), 256>>>(x, ln_w, ln_b);              // 3
    scan_kernel<<<scan_grid, 128>>>(A_log, Dp);                            // 4 <- ncu slot (diagnostic)
    hmma_gemm_in_kernel<<<dim3((2*DIN)/128, (B_*L_)/128), 256, SMEM_HMMA>>>();
    conv_silu_kernel<<<dim3(L_/64, DIN/32, B_), 256>>>(conv_w, conv_b);
    hmma_xproj_kernel<<<(B_*L_)/128, 256, SMEM_X>>>();
    dt_kernel<<<dim3(L_/32, DIN/64, B_), 256>>>(W_dt, b_dt);
    scan_pre_kernel<<<scan_grid, 128>>>(A_log);
    scan_mid_kernel<<<(B_*DIN*NST + 255)/256, 256>>>();
    scan_kernel<<<scan_grid, 128>>>(A_log, Dp);                            // real pass 3
    hmma_gemm_out_kernel<<<dim3((B_*L_)/128, C_/128), 256, SMEM_HMMA>>>(out);
}

// round 17
// speedup vs baseline: 3.0614x; 1.2446x over previous
#include <cuda_runtime.h>
#include <cuda_bf16.h>
#include <cstdint>

#define B_   2
#define C_   384
#define L_   8192
#define DIN  768
#define NST  16
#define DTR  24
#define XW   56        // dt_rank + 2*d_state
#define XWP  64        // padded rows of W_xproj for HMMA
#define SEG  128
#define SEGL (L_/SEG)  // 64

// ---------------- scratch (device globals; no allocation allowed) ----------------
__device__ float g_xi  [(size_t)B_*L_*DIN];    // (b*l, d)
__device__ float g_z   [(size_t)B_*L_*DIN];    // (b*l, d)
__device__ float g_xlt [(size_t)B_*L_*DIN];    // (b*l, d)  conv+silu output fp32 (scan)
__device__ float g_xdbl[(size_t)B_*L_*XW];     // (b*l, 56)
__device__ float g_dtl [(size_t)B_*L_*DIN];    // (b*l, d)  softplus(dt)
__device__ float g_segF[(size_t)B_*DIN*SEG*NST];   // segment final state (h0=0)
__device__ float g_segG[(size_t)B_*DIN*SEG*NST];   // segment decay
__device__ float g_segH[(size_t)B_*DIN*SEG*NST];   // segment entry state

// bf16 split operands for tensor-core GEMMs
__device__ __nv_bfloat16 g_xnh[(size_t)B_*L_*C_], g_xnl[(size_t)B_*L_*C_];       // xn   (b*l, c)
__device__ __nv_bfloat16 g_winh[(size_t)2*DIN*C_], g_winl[(size_t)2*DIN*C_];     // W_in
__device__ __nv_bfloat16 g_xch[(size_t)B_*L_*DIN], g_xcl[(size_t)B_*L_*DIN];     // xc   (b*l, d)
__device__ __nv_bfloat16 g_wxh[(size_t)XWP*DIN], g_wxl[(size_t)XWP*DIN];         // W_xproj padded
__device__ __nv_bfloat16 g_gh [(size_t)B_*L_*DIN], g_gl [(size_t)B_*L_*DIN];     // y*silu(z)
__device__ __nv_bfloat16 g_wouth[(size_t)C_*DIN], g_woutl[(size_t)C_*DIN];       // W_out

__device__ __forceinline__ float silu_f(float v) {
    return v * (1.f / (1.f + __expf(-v)));
}
__device__ __forceinline__ uint32_t smem_u32(const void* p) {
    uint32_t a;
    asm("{ .reg .u64 t; cvta.to.shared.u64 t, %1; cvt.u32.u64 %0, t; }" : "=r"(a) : "l"(p));
    return a;
}

// ================= async-copy / HMMA building blocks (base sm_103 legal) =================
#define CP16(dst, src) \
    asm volatile("cp.async.cg.shared.global [%0], [%1], 16;" :: "r"(dst), "l"(src))
#define CP_COMMIT() asm volatile("cp.async.commit_group;" ::: "memory")
#define CP_WAIT1()  asm volatile("cp.async.wait_group 1;" ::: "memory")
#define CP_WAIT0()  asm volatile("cp.async.wait_group 0;" ::: "memory")

__device__ __forceinline__ void ldsm4(uint32_t r[4], uint32_t addr) {
    asm volatile("ldmatrix.sync.aligned.m8n8.x4.shared.b16 {%0,%1,%2,%3}, [%4];"
        : "=r"(r[0]), "=r"(r[1]), "=r"(r[2]), "=r"(r[3]) : "r"(addr));
}
__device__ __forceinline__ void mma16816(float d[4], const uint32_t a[4],
                                         uint32_t b0, uint32_t b1) {
    asm volatile("mma.sync.aligned.m16n8k16.row.col.f32.bf16.bf16.f32 "
        "{%0,%1,%2,%3}, {%4,%5,%6,%7}, {%8,%9}, {%0,%1,%2,%3};"
        : "+f"(d[0]), "+f"(d[1]), "+f"(d[2]), "+f"(d[3])
        : "r"(a[0]), "r"(a[1]), "r"(a[2]), "r"(a[3]), "r"(b0), "r"(b1));
}

// ---------- 128x128 mainloop: 3-stage cp.async pipeline, one barrier per chunk ----------
__device__ __forceinline__ void stage_chunk(uint32_t sbuf,
        const __nv_bfloat16* __restrict__ Ah, const __nv_bfloat16* __restrict__ Al,
        int arow0, int lda,
        const __nv_bfloat16* __restrict__ Bh, const __nv_bfloat16* __restrict__ Bl,
        int brow0, int ldb, int kc, int tid) {
    const __nv_bfloat16* srcs[4] = {Ah, Al, Bh, Bl};
    #pragma unroll
    for (int tile = 0; tile < 4; tile++) {
        const __nv_bfloat16* src = srcs[tile];
        int ld = (tile < 2) ? lda : ldb;
        int r0 = (tile < 2) ? arow0 : brow0;
        #pragma unroll
        for (int h = 0; h < 2; h++) {
            int cid = tid + h * 256;
            int row = cid >> 2, ch = cid & 3;
            const void* g = src + (size_t)(r0 + row) * ld + kc * 32 + ch * 8;
            uint32_t d = sbuf + tile * 8192 + row * 64 + ((ch ^ ((row >> 1) & 3)) << 4);
            CP16(d, g);
        }
    }
}
__device__ __forceinline__ void compute_chunk(uint32_t sbuf, int warp_m, int warp_n,
                                              int lane, float acc[4][4][4]) {
    int arow = lane & 15;
    int akc  = lane >> 4;
    int bro  = (lane & 7) + ((lane >> 4) << 3);
    int bkc  = (lane >> 3) & 1;
    #pragma unroll
    for (int k16 = 0; k16 < 2; k16++) {
        uint32_t ah[4][4], al[4][4], bhf[2][4], blf[2][4];
        #pragma unroll
        for (int mi = 0; mi < 4; mi++) {
            int row = warp_m * 64 + mi * 16 + arow;
            int ch = k16 * 2 + akc;
            uint32_t off = row * 64 + ((ch ^ ((row >> 1) & 3)) << 4);
            ldsm4(ah[mi], sbuf + off);
            ldsm4(al[mi], sbuf + 8192 + off);
        }
        #pragma unroll
        for (int p = 0; p < 2; p++) {
            int row = warp_n * 32 + p * 16 + bro;
            int ch = k16 * 2 + bkc;
            uint32_t off = row * 64 + ((ch ^ ((row >> 1) & 3)) << 4);
            ldsm4(bhf[p], sbuf + 16384 + off);
            ldsm4(blf[p], sbuf + 24576 + off);
        }
        #pragma unroll
        for (int mi = 0; mi < 4; mi++)
            #pragma unroll
            for (int nj = 0; nj < 4; nj++) {
                int p = nj >> 1, w = (nj & 1) * 2;
                mma16816(acc[mi][nj], ah[mi], bhf[p][w], bhf[p][w + 1]);
                mma16816(acc[mi][nj], ah[mi], blf[p][w], blf[p][w + 1]);
                mma16816(acc[mi][nj], al[mi], bhf[p][w], bhf[p][w + 1]);
            }
    }
}
__device__ __forceinline__ void mma_mainloop(char* smem, int tid,
        const __nv_bfloat16* Ah, const __nv_bfloat16* Al, int arow0, int lda,
        const __nv_bfloat16* Bh, const __nv_bfloat16* Bl, int brow0, int ldb,
        int nch, float acc[4][4][4]) {
    uint32_t sb = smem_u32(smem);
    int warp_m = (tid >> 5) >> 2, warp_n = (tid >> 5) & 3, lane = tid & 31;
    #pragma unroll
    for (int mi = 0; mi < 4; mi++)
        #pragma unroll
        for (int nj = 0; nj < 4; nj++)
            #pragma unroll
            for (int r = 0; r < 4; r++) acc[mi][nj][r] = 0.f;
    stage_chunk(sb, Ah, Al, arow0, lda, Bh, Bl, brow0, ldb, 0, tid);
    CP_COMMIT();
    stage_chunk(sb + 32768, Ah, Al, arow0, lda, Bh, Bl, brow0, ldb, 1, tid);
    CP_COMMIT();
    for (int c = 0; c < nch; c++) {
        if (c + 1 < nch) CP_WAIT1(); else CP_WAIT0();
        __syncthreads();
        compute_chunk(sb + (c % 3) * 32768, warp_m, warp_n, lane, acc);
        if (c + 2 < nch) {
            stage_chunk(sb + ((c + 2) % 3) * 32768, Ah, Al, arow0, lda,
                        Bh, Bl, brow0, ldb, c + 2, tid);
            CP_COMMIT();
        }
    }
}
#define SMEM_HMMA (3 * 32768)

// ---------- 128x64 mainloop for xproj (2-stage, proven) ----------
__device__ __forceinline__ void stage_chunk_x(uint32_t sbuf, int kc, int arow0, int tid) {
    #pragma unroll
    for (int h = 0; h < 2; h++) {
        int cid = tid + h * 256;
        int row = cid >> 2, ch = cid & 3;
        const void* gh_ = g_xch + (size_t)(arow0 + row) * DIN + kc * 32 + ch * 8;
        const void* gl_ = g_xcl + (size_t)(arow0 + row) * DIN + kc * 32 + ch * 8;
        uint32_t off = row * 64 + ((ch ^ ((row >> 1) & 3)) << 4);
        CP16(sbuf + off, gh_);
        CP16(sbuf + 8192 + off, gl_);
    }
    {
        int row = tid >> 2, ch = tid & 3;
        const void* gh_ = g_wxh + (size_t)row * DIN + kc * 32 + ch * 8;
        const void* gl_ = g_wxl + (size_t)row * DIN + kc * 32 + ch * 8;
        uint32_t off = row * 64 + ((ch ^ ((row >> 1) & 3)) << 4);
        CP16(sbuf + 16384 + off, gh_);
        CP16(sbuf + 20480 + off, gl_);
    }
}
__device__ __forceinline__ void compute_chunk_x(uint32_t sbuf, int warp_m, int warp_n,
                                                int lane, float acc[2][4][4]) {
    int arow = lane & 15;
    int akc  = lane >> 4;
    int bro  = (lane & 7) + ((lane >> 4) << 3);
    int bkc  = (lane >> 3) & 1;
    #pragma unroll
    for (int k16 = 0; k16 < 2; k16++) {
        uint32_t ah[2][4], al[2][4], bhf[2][4], blf[2][4];
        #pragma unroll
        for (int mi = 0; mi < 2; mi++) {
            int row = warp_m * 32 + mi * 16 + arow;
            int ch = k16 * 2 + akc;
            uint32_t off = row * 64 + ((ch ^ ((row >> 1) & 3)) << 4);
            ldsm4(ah[mi], sbuf + off);
            ldsm4(al[mi], sbuf + 8192 + off);
        }
        #pragma unroll
        for (int p = 0; p < 2; p++) {
            int row = warp_n * 32 + p * 16 + bro;
            int ch = k16 * 2 + bkc;
            uint32_t off = row * 64 + ((ch ^ ((row >> 1) & 3)) << 4);
            ldsm4(bhf[p], sbuf + 16384 + off);
            ldsm4(blf[p], sbuf + 20480 + off);
        }
        #pragma unroll
        for (int mi = 0; mi < 2; mi++)
            #pragma unroll
            for (int nj = 0; nj < 4; nj++) {
                int p = nj >> 1, w = (nj & 1) * 2;
                mma16816(acc[mi][nj], ah[mi], bhf[p][w], bhf[p][w + 1]);
                mma16816(acc[mi][nj], ah[mi], blf[p][w], blf[p][w + 1]);
                mma16816(acc[mi][nj], al[mi], bhf[p][w], bhf[p][w + 1]);
            }
    }
}
#define SMEM_X (2 * 24576)

__global__ void __launch_bounds__(256) hmma_xproj_kernel() {
    extern __shared__ char smem[];
    uint32_t sb = smem_u32(smem);
    int tid = threadIdx.x;
    int bm = blockIdx.x;
    int arow0 = bm * 128;
    int warp = tid >> 5, lane = tid & 31;
    int warp_m = warp >> 1, warp_n = warp & 1;
    float acc[2][4][4];
    #pragma unroll
    for (int mi = 0; mi < 2; mi++)
        #pragma unroll
        for (int nj = 0; nj < 4; nj++)
            #pragma unroll
            for (int r = 0; r < 4; r++) acc[mi][nj][r] = 0.f;
    stage_chunk_x(sb, 0, arow0, tid);
    CP_COMMIT();
    const int nch = DIN / 32;
    for (int c = 0; c < nch; c++) {
        if (c + 1 < nch) {
            stage_chunk_x(sb + ((c + 1) & 1) * 24576, c + 1, arow0, tid);
            CP_COMMIT();
            CP_WAIT1();
        } else {
            CP_WAIT0();
        }
        __syncthreads();
        compute_chunk_x(sb + (c & 1) * 24576, warp_m, warp_n, lane, acc);
        __syncthreads();
    }
    int g = lane >> 2, t = lane & 3;
    #pragma unroll
    for (int mi = 0; mi < 2; mi++) {
        int row = arow0 + warp_m * 32 + mi * 16 + g;
        #pragma unroll
        for (int nj = 0; nj < 4; nj++) {
            int col = warp_n * 32 + nj * 8 + 2 * t;
            if (col < XW) {
                *(float2*)(g_xdbl + (size_t)row * XW + col)       = make_float2(acc[mi][nj][0], acc[mi][nj][1]);
                *(float2*)(g_xdbl + (size_t)(row + 8) * XW + col) = make_float2(acc[mi][nj][2], acc[mi][nj][3]);
            }
        }
    }
}

// ---------------- tensor GEMM 1: xz = xn @ W_in^T -> g_xi / g_z ----------------
__global__ void __launch_bounds__(256) hmma_gemm_in_kernel() {
    extern __shared__ char smem[];
    int tid = threadIdx.x;
    int bn = blockIdx.x, bm = blockIdx.y;
    float acc[4][4][4];
    mma_mainloop(smem, tid, g_xnh, g_xnl, bm * 128, C_,
                 g_winh, g_winl, bn * 128, C_, C_ / 32, acc);
    int warp_m = (tid >> 5) >> 2, warp_n = (tid >> 5) & 3, lane = tid & 31;
    int g = lane >> 2, t = lane & 3;
    int col0 = bn * 128;
    float* dst = (col0 < DIN) ? g_xi : g_z;
    int cbase = ((col0 < DIN) ? col0 : col0 - DIN) + warp_n * 32;
    #pragma unroll
    for (int mi = 0; mi < 4; mi++) {
        int row = bm * 128 + warp_m * 64 + mi * 16 + g;
        #pragma unroll
        for (int nj = 0; nj < 4; nj++) {
            int col = cbase + nj * 8 + 2 * t;
            *(float2*)(dst + (size_t)row * DIN + col)       = make_float2(acc[mi][nj][0], acc[mi][nj][1]);
            *(float2*)(dst + (size_t)(row + 8) * DIN + col) = make_float2(acc[mi][nj][2], acc[mi][nj][3]);
        }
    }
}

// ---------------- tensor GEMM 2: out = W_out x gate^T, store (b,c,l) ----------------
__global__ void __launch_bounds__(256) hmma_gemm_out_kernel(float* __restrict__ out) {
    extern __shared__ char smem[];
    int tid = threadIdx.x;
    int bn = blockIdx.x, bm = blockIdx.y;
    float acc[4][4][4];
    mma_mainloop(smem, tid, g_wouth, g_woutl, bm * 128, DIN,
                 g_gh, g_gl, bn * 128, DIN, DIN / 32, acc);
    int warp_m = (tid >> 5) >> 2, warp_n = (tid >> 5) & 3, lane = tid & 31;
    int g = lane >> 2, t = lane & 3;
    int nrow0 = bn * 128 + warp_n * 32;
    int b = nrow0 / L_;
    #pragma unroll
    for (int mi = 0; mi < 4; mi++) {
        int c = bm * 128 + warp_m * 64 + mi * 16 + g;
        #pragma unroll
        for (int nj = 0; nj < 4; nj++) {
            int l = (nrow0 % L_) + nj * 8 + 2 * t;
            *(float2*)(out + ((size_t)(b * C_ + c)) * L_ + l)     = make_float2(acc[mi][nj][0], acc[mi][nj][1]);
            *(float2*)(out + ((size_t)(b * C_ + c + 8)) * L_ + l) = make_float2(acc[mi][nj][2], acc[mi][nj][3]);
        }
    }
}

// ---------------- weight splits ----------------
#define N_WIN  (2*DIN*C_)
#define N_WOUT (C_*DIN)
#define N_WX   (XWP*DIN)
__global__ void cvt_w1_kernel(const float* __restrict__ W_in) {
    int i = blockIdx.x * 256 + threadIdx.x;
    if (i >= N_WIN) return;
    float v = W_in[i];
    __nv_bfloat16 hi = __float2bfloat16(v);
    g_winh[i] = hi;
    g_winl[i] = __float2bfloat16(v - __bfloat162float(hi));
}
__global__ void cvt_w2_kernel(const float* __restrict__ W_out, const float* __restrict__ Wx) {
    int i = blockIdx.x * 256 + threadIdx.x;
    float v; __nv_bfloat16 *h, *l; int j;
    if (i < N_WOUT) {
        j = i; v = W_out[j]; h = g_wouth; l = g_woutl;
    } else if (i < N_WOUT + N_WX) {
        j = i - N_WOUT;
        int r = j / DIN;
        v = (r < XW) ? Wx[(size_t)r * DIN + (j % DIN)] : 0.f;
        h = g_wxh; l = g_wxl;
    } else return;
    __nv_bfloat16 hi = __float2bfloat16(v);
    h[j] = hi;
    l[j] = __float2bfloat16(v - __bfloat162float(hi));
}

// ---------------- fused LayerNorm: stats + apply + transpose + bf16 split ----------------
__global__ void __launch_bounds__(256) ln_fused_kernel(const float* __restrict__ x,
        const float* __restrict__ w, const float* __restrict__ bb) {
    __shared__ float s[C_ * 17];          // [c][l] stride 17
    __shared__ float rs_[256], rss[256];
    __shared__ float smu[16], srs[16];
    int l0 = blockIdx.x * 16, b = blockIdx.y;
    int tid = threadIdx.x;
    #pragma unroll
    for (int q = 0; q < 6; q++) {
        int id = tid + q * 256;
        int c = id >> 2, j = id & 3;
        float4 v = *(const float4*)(x + ((size_t)(b * C_ + c)) * L_ + l0 + j * 4);
        float* p = s + c * 17 + j * 4;
        p[0] = v.x; p[1] = v.y; p[2] = v.z; p[3] = v.w;
    }
    __syncthreads();
    {
        int l = tid & 15, gr = tid >> 4;
        float sum = 0.f, ss = 0.f;
        for (int c = gr; c < C_; c += 16) {
            float v = s[c * 17 + l];
            sum += v; ss += v * v;
        }
        rs_[tid] = sum; rss[tid] = ss;
        __syncthreads();
        #pragma unroll
        for (int off = 8; off > 0; off >>= 1) {
            if (gr < off) { rs_[tid] += rs_[tid + off * 16]; rss[tid] += rss[tid + off * 16]; }
            __syncthreads();
        }
        if (gr == 0) {
            float mu = rs_[l] * (1.f / C_);
            float var = rss[l] * (1.f / C_) - mu * mu;
            smu[l] = mu; srs[l] = rsqrtf(var + 1e-5f);
        }
        __syncthreads();
    }
    #pragma unroll
    for (int q = 0; q < 24; q++) {
        int e = tid + q * 256;
        int l = e / C_, c = e % C_;
        float v = (s[c * 17 + l] - smu[l]) * srs[l] * w[c] + bb[c];
        __nv_bfloat16 hi = __float2bfloat16(v);
        size_t idx = (size_t)(b * L_ + l0 + l) * C_ + c;
        g_xnh[idx] = hi;
        g_xnl[idx] = __float2bfloat16(v - __bfloat162float(hi));
    }
}

// ---------------- depthwise causal conv (k=4) + SiLU; fp32 + bf16 split, all (b*l,d) ----------------
__global__ void __launch_bounds__(256) conv_silu_kernel(const float* __restrict__ cw,
                                                        const float* __restrict__ cb) {
    __shared__ float s[67][36];
    __shared__ float sout[64][33];
    int l0 = blockIdx.x * 64, d0 = blockIdx.y * 32, b = blockIdx.z;
    int tid = threadIdx.x;
    for (int idx = tid; idx < 67 * 8; idx += 256) {
        int li = idx >> 3, d4 = idx & 7;
        int gl = l0 + li - 3;
        float4 v = make_float4(0.f, 0.f, 0.f, 0.f);
        if (gl >= 0) v = *(const float4*)(g_xi + ((size_t)(b*L_ + gl))*DIN + d0 + d4*4);
        *(float4*)&s[li][d4 * 4] = v;
    }
    __syncthreads();
    #pragma unroll
    for (int q = 0; q < 2; q++) {
        int item = tid + q * 256;
        int dd = item >> 4, lq = item & 15;
        int ll = lq * 4;
        int d = d0 + dd;
        float4 wv = *(const float4*)(cw + d * 4);
        float bias = cb[d];
        #pragma unroll
        for (int j = 0; j < 4; j++) {
            float acc = bias + wv.x * s[ll + j][dd] + wv.y * s[ll + j + 1][dd]
                             + wv.z * s[ll + j + 2][dd] + wv.w * s[ll + j + 3][dd];
            sout[ll + j][dd] = silu_f(acc);
        }
    }
    __syncthreads();
    #pragma unroll
    for (int q = 0; q < 8; q++) {
        int idx = tid + q * 256;
        int ll = idx >> 5, dd = idx & 31;
        float v = sout[ll][dd];
        __nv_bfloat16 hi = __float2bfloat16(v);
        size_t gi = (size_t)(b*L_ + l0 + ll)*DIN + d0 + dd;
        g_xlt[gi] = v;
        g_xch[gi] = hi;
        g_xcl[gi] = __float2bfloat16(v - __bfloat162float(hi));
    }
}

// ---------------- dt = softplus(x_dbl[:, :24] @ W_dt^T + b_dt) -> (b*l, d) ----------------
__global__ void dt_kernel(const float* __restrict__ Wdt, const float* __restrict__ bdt) {
    __shared__ float xs[32][25];
    __shared__ float ws[64][25];
    __shared__ float bs[64];
    int l0 = blockIdx.x * 32, d0 = blockIdx.y * 64, b = blockIdx.z;
    int tid = threadIdx.x;
    for (int idx = tid; idx < 32*24; idx += 256) {
        int ll = idx / 24, r = idx % 24;
        xs[ll][r] = g_xdbl[(size_t)(b*L_ + l0 + ll)*XW + r];
    }
    for (int idx = tid; idx < 64*24; idx += 256) {
        int dd = idx / 24, r = idx % 24;
        ws[dd][r] = Wdt[(size_t)(d0+dd)*DTR + r];
    }
    if (tid < 64) bs[tid] = bdt[d0 + tid];
    __syncthreads();
    #pragma unroll
    for (int t = 0; t < 8; t++) {
        int idx = tid + t*256;
        int dd = idx & 63, ll = idx >> 6;   // warp varies d -> coalesced (b*l,d) store
        float acc = bs[dd];
        #pragma unroll
        for (int r = 0; r < 24; r++) acc = fmaf(xs[ll][r], ws[dd][r], acc);
        float sp = (acc > 20.f) ? acc : log1pf(expf(acc));
        g_dtl[((size_t)(b*L_ + l0 + ll))*DIN + d0 + dd] = sp;
    }
}

// ---------------- scan v8: thread-per-(d,seg), SEG=128 -> 6144 warps ----------------
__device__ __forceinline__ void load_a16(const float* __restrict__ Alog, int d, float a[16]) {
    const float4* ap = (const float4*)(Alog + d * NST);
    #pragma unroll
    for (int q = 0; q < 4; q++) {
        float4 v = ap[q];
        a[4*q+0] = -__expf(v.x); a[4*q+1] = -__expf(v.y);
        a[4*q+2] = -__expf(v.z); a[4*q+3] = -__expf(v.w);
    }
}

// pass 1: per-segment F (final state from h=0) and G_n = exp(a_n * sum dt)
__global__ void __launch_bounds__(128) scan_pre_kernel(const float* __restrict__ Alog) {
    int d = blockIdx.x * 128 + threadIdx.x;
    int seg = blockIdx.y, b = blockIdx.z;
    float a[16];
    load_a16(Alog, d, a);
    float h[16];
    #pragma unroll
    for (int n = 0; n < 16; n++) h[n] = 0.f;
    float sdt = 0.f;
    #pragma unroll 2
    for (int l = 0; l < SEGL; l++) {
        size_t base = (size_t)(b * L_ + seg * SEGL + l);
        float dt = g_dtl[base * DIN + d];
        float xv = g_xlt[base * DIN + d];
        const float4* bc4 = (const float4*)(g_xdbl + base * XW + DTR);
        float u = dt * xv;
        sdt += dt;
        #pragma unroll
        for (int q = 0; q < 4; q++) {
            float4 Bv = bc4[q];
            h[4*q+0] = fmaf(h[4*q+0], __expf(dt * a[4*q+0]), u * Bv.x);
            h[4*q+1] = fmaf(h[4*q+1], __expf(dt * a[4*q+1]), u * Bv.y);
            h[4*q+2] = fmaf(h[4*q+2], __expf(dt * a[4*q+2]), u * Bv.z);
            h[4*q+3] = fmaf(h[4*q+3], __expf(dt * a[4*q+3]), u * Bv.w);
        }
    }
    size_t off = ((size_t)(b * DIN + d) * SEG + seg) * NST;
    float4* F4 = (float4*)(g_segF + off);
    float4* G4 = (float4*)(g_segG + off);
    #pragma unroll
    for (int q = 0; q < 4; q++) {
        F4[q] = make_float4(h[4*q], h[4*q+1], h[4*q+2], h[4*q+3]);
        G4[q] = make_float4(__expf(sdt * a[4*q+0]), __expf(sdt * a[4*q+1]),
                            __expf(sdt * a[4*q+2]), __expf(sdt * a[4*q+3]));
    }
}

// pass 2: sequential combine of segment summaries -> entry state per segment
__global__ void scan_mid_kernel() {
    int i = blockIdx.x * 256 + threadIdx.x;          // (b*DIN+d)*NST+n
    if (i >= B_ * DIN * NST) return;
    size_t base = (size_t)(i / NST) * SEG * NST + (i % NST);
    float h = 0.f;
    #pragma unroll 8
    for (int s = 0; s < SEG; s++) {
        size_t o = base + (size_t)s * NST;
        g_segH[o] = h;
        h = g_segF[o] + g_segG[o] * h;
    }
}

// pass 3: full scan from entry state; fuses y*silu(z) gate + bf16 split output
__global__ void __launch_bounds__(128) scan_kernel(const float* __restrict__ Alog,
                                                   const float* __restrict__ Dp) {
    int d = blockIdx.x * 128 + threadIdx.x;
    int seg = blockIdx.y, b = blockIdx.z;
    float a[16];
    load_a16(Alog, d, a);
    float Dd = Dp[d];
    float h[16];
    {
        const float4* H4 = (const float4*)(g_segH + ((size_t)(b * DIN + d) * SEG + seg) * NST);
        #pragma unroll
        for (int q = 0; q < 4; q++) {
            float4 v = H4[q];
            h[4*q] = v.x; h[4*q+1] = v.y; h[4*q+2] = v.z; h[4*q+3] = v.w;
        }
    }
    #pragma unroll 2
    for (int l = 0; l < SEGL; l++) {
        size_t base = (size_t)(b * L_ + seg * SEGL + l);
        float dt = g_dtl[base * DIN + d];
        float xv = g_xlt[base * DIN + d];
        const float4* bc4 = (const float4*)(g_xdbl + base * XW + DTR);
        float u = dt * xv;
        float y0 = 0.f, y1 = 0.f, y2 = 0.f, y3 = 0.f;
        #pragma unroll
        for (int q = 0; q < 4; q++) {
            float4 Bv = bc4[q];
            float4 Cv = bc4[4 + q];
            h[4*q+0] = fmaf(h[4*q+0], __expf(dt * a[4*q+0]), u * Bv.x);
            y0 = fmaf(h[4*q+0], Cv.x, y0);
            h[4*q+1] = fmaf(h[4*q+1], __expf(dt * a[4*q+1]), u * Bv.y);
            y1 = fmaf(h[4*q+1], Cv.y, y1);
            h[4*q+2] = fmaf(h[4*q+2], __expf(dt * a[4*q+2]), u * Bv.z);
            y2 = fmaf(h[4*q+2], Cv.z, y2);
            h[4*q+3] = fmaf(h[4*q+3], __expf(dt * a[4*q+3]), u * Bv.w);
            y3 = fmaf(h[4*q+3], Cv.w, y3);
        }
        float y = ((y0 + y1) + (y2 + y3)) + xv * Dd;
        float zv = g_z[base * DIN + d];
        float gv = y * silu_f(zv);
        __nv_bfloat16 hi = __float2bfloat16(gv);
        g_gh[base * DIN + d] = hi;
        g_gl[base * DIN + d] = __float2bfloat16(gv - __bfloat162float(hi));
    }
}

// ---------------- launch ----------------
extern "C" void kernel_launch(void* const* d_in, const int* in_sizes, int n_in,
                              void* d_out, int out_size) {
    const float* x      = (const float*)d_in[0];
    const float* ln_w   = (const float*)d_in[1];
    const float* ln_b   = (const float*)d_in[2];
    const float* W_in   = (const float*)d_in[3];
    const float* conv_w = (const float*)d_in[4];
    const float* conv_b = (const float*)d_in[5];
    const float* W_xprj = (const float*)d_in[6];
    const float* W_dt   = (const float*)d_in[7];
    const float* b_dt   = (const float*)d_in[8];
    const float* A_log  = (const float*)d_in[9];
    const float* Dp     = (const float*)d_in[10];
    const float* W_out  = (const float*)d_in[11];
    float* out = (float*)d_out;

    static int smem_set = 0;
    if (!smem_set) {
        cudaFuncSetAttribute(hmma_gemm_in_kernel,  cudaFuncAttributeMaxDynamicSharedMemorySize, SMEM_HMMA);
        cudaFuncSetAttribute(hmma_gemm_out_kernel, cudaFuncAttributeMaxDynamicSharedMemorySize, SMEM_HMMA);
        cudaFuncSetAttribute(hmma_xproj_kernel,    cudaFuncAttributeMaxDynamicSharedMemorySize, SMEM_X);
        smem_set = 1;
    }

    dim3 scan_grid(DIN/128, SEG, B_);

    cvt_w1_kernel<<<(N_WIN + 255)/256, 256>>>(W_in);                       // 1
    cvt_w2_kernel<<<(N_WOUT + N_WX + 255)/256, 256>>>(W_out, W_xprj);      // 2
    ln_fused_kernel<<<dim3(L_/16, B_), 256>>>(x, ln_w, ln_b);              // 3
    hmma_gemm_in_kernel<<<dim3((2*DIN)/128, (B_*L_)/128), 256, SMEM_HMMA>>>();  // 4 <- ncu slot
    conv_silu_kernel<<<dim3(L_/64, DIN/32, B_), 256>>>(conv_w, conv_b);
    hmma_xproj_kernel<<<(B_*L_)/128, 256, SMEM_X>>>();
    dt_kernel<<<dim3(L_/32, DIN/64, B_), 256>>>(W_dt, b_dt);
    scan_pre_kernel<<<scan_grid, 128>>>(A_log);
    scan_mid_kernel<<<(B_*DIN*NST + 255)/256, 256>>>();
    scan_kernel<<<scan_grid, 128>>>(A_log, Dp);
    hmma_gemm_out_kernel<<<dim3((B_*L_)/128, C_/128), 256, SMEM_HMMA>>>(out);
}